// round 7
// baseline (speedup 1.0000x reference)
#include <cuda_runtime.h>
#include <math.h>

#define BB 8
#define MM 3072
#define CC 10
#define HH 128
#define KK 32
#define GG 24                 // grid cells per axis; 1/24 > 0.04 radius
#define NCELL (GG * GG)       // 576
#define CAP 48                // per-particle candidate-hit capacity (lambda~15)
#define NPW 8                 // particles (=warps) per 256-thread block
#define FROW 28               // feature row stride in floats (112B, 16B-aligned)
#define RADIUSF 0.04f
#define ACC_SCALEF 0.02f
#define MAX_VELF 0.02f
#define NOISEF 0.002f

typedef unsigned long long ull;

// Scratch (no cudaMalloc allowed)
__device__ float4 g_sorted[BB * MM];            // {x, y, id_as_float_bits, pad}
__device__ int    g_cell_off[BB * (NCELL + 1)]; // exclusive offsets per batch

__device__ __forceinline__ int cell_of(float p) {
    int c = (int)(p * (float)GG);
    return c > GG - 1 ? GG - 1 : c;
}

// ---- f32x2 packed helpers (sm_100+) ---------------------------------------
__device__ __forceinline__ ull pack2(float lo, float hi) {
    ull d; asm("mov.b64 %0, {%1, %2};" : "=l"(d) : "f"(lo), "f"(hi)); return d;
}
__device__ __forceinline__ void unpack2(ull v, float &lo, float &hi) {
    asm("mov.b64 {%0, %1}, %2;" : "=f"(lo), "=f"(hi) : "l"(v));
}
__device__ __forceinline__ ull fma2(ull a, ull b, ull c) {
    ull d; asm("fma.rn.f32x2 %0, %1, %2, %3;" : "=l"(d) : "l"(a), "l"(b), "l"(c));
    return d;
}
__device__ __forceinline__ ull add2(ull a, ull b) {
    ull d; asm("add.rn.f32x2 %0, %1, %2;" : "=l"(d) : "l"(a), "l"(b));
    return d;
}
__device__ __forceinline__ void lds2x64(ull &a, ull &b, unsigned addr) {
    asm volatile("ld.shared.v2.b64 {%0, %1}, [%2];" : "=l"(a), "=l"(b) : "r"(addr));
}
__device__ __forceinline__ void lds64(ull &a, unsigned addr) {
    asm volatile("ld.shared.b64 %0, [%1];" : "=l"(a) : "r"(addr));
}
__device__ __forceinline__ unsigned smem_u32(const void* p) {
    return (unsigned)__cvta_generic_to_shared(p);
}

// ---------------------------------------------------------------------------
// Kernel 0: build cell-sorted particle list. One block per batch.
// ---------------------------------------------------------------------------
#define TPB_G 1024
__global__ void __launch_bounds__(TPB_G) build_grid_kernel(const float* __restrict__ x)
{
    __shared__ int s_cnt[NCELL];
    __shared__ int s_wsum[TPB_G / 32];
    __shared__ int s_cur[NCELL];

    const int b = blockIdx.x;
    const int tid = threadIdx.x;
    const int wid = tid >> 5, lane = tid & 31;
    const unsigned FULL = 0xffffffffu;
    const float* xb = x + (size_t)b * MM * CC;

    if (tid < NCELL) s_cnt[tid] = 0;
    __syncthreads();

    int   myc[MM / TPB_G];
    float mpx[MM / TPB_G], mpy[MM / TPB_G];
    #pragma unroll
    for (int r = 0; r < MM / TPB_G; r++) {
        const int i = tid + r * TPB_G;
        const float px = xb[(size_t)i * CC + 0];
        const float py = xb[(size_t)i * CC + 1];
        const int c = cell_of(py) * GG + cell_of(px);
        myc[r] = c; mpx[r] = px; mpy[r] = py;
        atomicAdd(&s_cnt[c], 1);
    }
    __syncthreads();

    // hierarchical exclusive scan over NCELL=576
    int val = (tid < NCELL) ? s_cnt[tid] : 0;
    int incl = val;
    #pragma unroll
    for (int o = 1; o < 32; o <<= 1) {
        int v = __shfl_up_sync(FULL, incl, o);
        if (lane >= o) incl += v;
    }
    if (lane == 31) s_wsum[wid] = incl;
    __syncthreads();
    if (wid == 0) {
        int wv = (lane < TPB_G / 32) ? s_wsum[lane] : 0;
        int wi = wv;
        #pragma unroll
        for (int o = 1; o < 32; o <<= 1) {
            int v = __shfl_up_sync(FULL, wi, o);
            if (lane >= o) wi += v;
        }
        if (lane < TPB_G / 32) s_wsum[lane] = wi - wv;
    }
    __syncthreads();
    if (tid < NCELL) {
        const int excl = s_wsum[wid] + incl - val;
        s_cur[tid] = excl;
        g_cell_off[b * (NCELL + 1) + tid] = excl;
    }
    if (tid == 0) g_cell_off[b * (NCELL + 1) + NCELL] = MM;
    __syncthreads();

    #pragma unroll
    for (int r = 0; r < MM / TPB_G; r++) {
        const int i = tid + r * TPB_G;
        const int slot = atomicAdd(&s_cur[myc[r]], 1);
        g_sorted[(size_t)b * MM + slot] =
            make_float4(mpx[r], mpy[r], __int_as_float(i), 0.0f);
    }
}

// ---------------------------------------------------------------------------
// Fused kernel: one warp per particle, warp-autonomous.
//  Gather: 6 STS.128 of dup-pairs, 112B row stride (4-way instead of 8-way
//  conflicts). MLP: 4 hidden/lane, 4 independent FFMA2 sub-chains (depth 6).
// ---------------------------------------------------------------------------
__global__ void __launch_bounds__(256, 4) fused_kernel(
    const float* __restrict__ x,  const float* __restrict__ W1,
    const float* __restrict__ b1, const float* __restrict__ W2,
    const float* __restrict__ b2, const float* __restrict__ noise_u,
    float* __restrict__ out)
{
    __shared__ float s_cdx[NPW][CAP], s_cdy[NPW][CAP], s_cds[NPW][CAP];
    __shared__ int   s_cj [NPW][CAP];
    __shared__ __align__(16) float s_feat[NPW][KK * FROW];
    __shared__ int   s_astart[NPW][9];
    __shared__ int   s_bound [NPW][10];

    const unsigned FULL = 0xffffffffu;
    const int warp = threadIdx.x >> 5;
    const int lane = threadIdx.x & 31;
    const int p = warp;
    const int s = blockIdx.x * NPW + p;          // global sorted slot
    const int b = s / MM;
    const int myslot = s - b * MM;

    const float4 me = g_sorted[s];
    const float pix = me.x, piy = me.y;
    const int   myid = __float_as_int(me.z);
    const int   grow = b * MM + myid;

    // ======================= Phase 1: search =================================
    const int cix = cell_of(pix);
    const int ciy = cell_of(piy);
    int len = 0, t0 = 0;
    if (lane < 9) {
        int cy = ciy + (lane / 3) - 1; if (cy < 0) cy += GG; if (cy >= GG) cy -= GG;
        int cx = cix + (lane % 3) - 1; if (cx < 0) cx += GG; if (cx >= GG) cx -= GG;
        const int c = cy * GG + cx;
        t0  = g_cell_off[b * (NCELL + 1) + c];
        len = g_cell_off[b * (NCELL + 1) + c + 1] - t0;
    }
    int incl = len;
    #pragma unroll
    for (int o = 1; o < 16; o <<= 1) {
        int v = __shfl_up_sync(FULL, incl, o);
        if (lane >= o) incl += v;
    }
    const int T = __shfl_sync(FULL, incl, 8);
    if (lane < 9) {
        const int excl = incl - len;
        s_astart[p][lane] = t0 - excl;
        s_bound [p][lane] = excl;
    }
    __syncwarp();

    const float4* __restrict__ sb = g_sorted + (size_t)b * MM;
    int hits = 0;
    for (int base = 0; base < T; base += 32) {
        const int k = base + lane;
        bool pred = false;
        int  cid = 0;
        float dx = 0.f, dy = 0.f, dist = 0.f;
        if (k < T) {
            int q = 0;
            #pragma unroll
            for (int t = 1; t < 9; t++)
                if (k >= s_bound[p][t]) q = t;
            const int tslot = s_astart[p][q] + k;
            const float4 cand = __ldg(&sb[tslot]);
            dx = pix - cand.x; dx -= rintf(dx);
            dy = piy - cand.y; dy -= rintf(dy);
            dist = sqrtf(dx * dx + dy * dy + 1e-12f);
            pred = (dist < RADIUSF) && (tslot != myslot);
            cid = __float_as_int(cand.z);
        }
        const unsigned m = __ballot_sync(FULL, pred);
        if (pred) {
            const int pos = hits + __popc(m & ((1u << lane) - 1));
            if (pos < CAP) {
                s_cj [p][pos] = cid;
                s_cdx[p][pos] = dx;
                s_cdy[p][pos] = dy;
                s_cds[p][pos] = dist;
            }
        }
        hits += __popc(m);
    }
    if (hits > CAP) hits = CAP;
    __syncwarp();

    // rare: rank-select KK nearest, staged through s_feat (edge order is dead:
    // the reference sums over edges)
    if (hits > KK) {
        float* stage = &s_feat[p][0];
        int*   stagei = (int*)&s_feat[p][3 * KK];
        for (int h = lane; h < hits; h += 32) {
            const float dh = s_cds[p][h];
            int rank = 0;
            for (int g2 = 0; g2 < hits; g2++) {
                const float dg = s_cds[p][g2];
                rank += (dg < dh) || (dg == dh && g2 < h);
            }
            if (rank < KK) {
                stage[rank]          = s_cdx[p][h];
                stage[KK + rank]     = s_cdy[p][h];
                stage[2 * KK + rank] = dh;
                stagei[rank]         = s_cj[p][h];
            }
        }
        __syncwarp();
        if (lane < KK) {
            s_cdx[p][lane] = stage[lane];
            s_cdy[p][lane] = stage[KK + lane];
            s_cds[p][lane] = stage[2 * KK + lane];
            s_cj [p][lane] = stagei[lane];
        }
        hits = KK;
        __syncwarp();
    }
    const int cnt = hits;

    const bool is_cell = (__ldg(&x[(size_t)grow * CC + 4]) == 1.0f);

    // ============== Phase 2: gather features (lane = edge) ===================
    float c4v = 0.0f;
    if (lane < cnt) {
        const int j = s_cj[p][lane];
        const float2* xp = (const float2*)(x + ((size_t)b * MM + j) * CC);
        const float2 a2 = __ldg(&xp[2]);    // cell, rest0
        c4v = a2.x;
        if (is_cell) {
            const float2 a1 = __ldg(&xp[1]);
            const float2 a3 = __ldg(&xp[3]);
            const float2 a4 = __ldg(&xp[4]);
            float4* row = (float4*)&s_feat[p][lane * FROW];
            const float ds = s_cds[p][lane];
            const float dx = s_cdx[p][lane];
            const float dy = s_cdy[p][lane];
            row[0] = make_float4(a1.x, a1.x, a1.y, a1.y);  // f0,f0,f1,f1
            row[1] = make_float4(a2.x, a2.x, a2.y, a2.y);  // f2,f2,f3,f3
            row[2] = make_float4(a3.x, a3.x, a3.y, a3.y);  // f4,f4,f5,f5
            row[3] = make_float4(a4.x, a4.x, a4.y, a4.y);  // f6,f6,f7,f7
            row[4] = make_float4(ds,   ds,   dx,   dx);    // f8,f8,f9,f9
            row[5] = make_float4(dy,   dy,   0.f,  0.f);   // f10,f10,pad
        }
    }
    const int deg_cell = __popc(__ballot_sync(FULL, (lane < cnt) && (c4v == 1.0f)));
    __syncwarp();

    // ===================== Phase 3: edge MLP (packed) ========================
    float o0 = 0.0f, o1 = 0.0f;

    if (is_cell) {
        float agg0 = 0.f, agg1 = 0.f, agg2 = 0.f, agg3 = 0.f;
        const int hA0 = lane,      hA1 = lane + 32;
        const int hB0 = lane + 64, hB1 = lane + 96;

        if (cnt > 0) {
            ull wA[11], wB[11];
            #pragma unroll
            for (int f = 0; f < 11; f++) {
                float a0 = __ldg(&W1[f * HH + hA0]);
                float a1v = __ldg(&W1[f * HH + hA1]);
                float bz0 = __ldg(&W1[f * HH + hB0]);
                float bz1 = __ldg(&W1[f * HH + hB1]);
                if (f == 2) {   // fold duplicated feature: msg[11] == msg[2]
                    a0  += __ldg(&W1[11 * HH + hA0]);
                    a1v += __ldg(&W1[11 * HH + hA1]);
                    bz0 += __ldg(&W1[11 * HH + hB0]);
                    bz1 += __ldg(&W1[11 * HH + hB1]);
                }
                wA[f] = pack2(a0, a1v);
                wB[f] = pack2(bz0, bz1);
            }
            const ull bA = pack2(__ldg(&b1[hA0]), __ldg(&b1[hA1]));
            const ull bB = pack2(__ldg(&b1[hB0]), __ldg(&b1[hB1]));
            const ull z64 = pack2(0.f, 0.f);

            unsigned raddr = smem_u32(&s_feat[p][0]);
            for (int e = 0; e < cnt; e++, raddr += FROW * 4) {
                ull q0, q1, q2, q3;
                // 4 independent sub-chains: depth <= 6
                ull tA0 = bA, tA1 = z64, tB0 = bB, tB1 = z64;
                lds2x64(q0, q1, raddr);          // f0, f1
                lds2x64(q2, q3, raddr + 16);     // f2, f3
                tA0 = fma2(q0, wA[0], tA0);  tB0 = fma2(q0, wB[0], tB0);
                tA1 = fma2(q1, wA[1], tA1);  tB1 = fma2(q1, wB[1], tB1);
                lds2x64(q0, q1, raddr + 32);     // f4, f5
                tA0 = fma2(q2, wA[2], tA0);  tB0 = fma2(q2, wB[2], tB0);
                tA1 = fma2(q3, wA[3], tA1);  tB1 = fma2(q3, wB[3], tB1);
                lds2x64(q2, q3, raddr + 48);     // f6, f7
                tA0 = fma2(q0, wA[4], tA0);  tB0 = fma2(q0, wB[4], tB0);
                tA1 = fma2(q1, wA[5], tA1);  tB1 = fma2(q1, wB[5], tB1);
                lds2x64(q0, q1, raddr + 64);     // f8, f9
                tA0 = fma2(q2, wA[6], tA0);  tB0 = fma2(q2, wB[6], tB0);
                tA1 = fma2(q3, wA[7], tA1);  tB1 = fma2(q3, wB[7], tB1);
                lds64(q2, raddr + 80);           // f10
                tA0 = fma2(q0, wA[8], tA0);  tB0 = fma2(q0, wB[8], tB0);
                tA1 = fma2(q1, wA[9], tA1);  tB1 = fma2(q1, wB[9], tB1);
                tA0 = fma2(q2, wA[10], tA0); tB0 = fma2(q2, wB[10], tB0);

                const ull tA = add2(tA0, tA1);
                const ull tB = add2(tB0, tB1);
                float u0, u1, u2, u3;
                unpack2(tA, u0, u1);
                unpack2(tB, u2, u3);
                agg0 += fmaxf(u0, 0.0f);
                agg1 += fmaxf(u1, 0.0f);
                agg2 += fmaxf(u2, 0.0f);
                agg3 += fmaxf(u3, 0.0f);
            }
        }

        // agg @ W2[:, 0:2]  (outputs 2..6 are dead code in the reference)
        float pa0, pa1;
        pa0 = agg0 * __ldg(&W2[hA0 * 7 + 0]);
        pa0 = fmaf(agg1, __ldg(&W2[hA1 * 7 + 0]), pa0);
        pa0 = fmaf(agg2, __ldg(&W2[hB0 * 7 + 0]), pa0);
        pa0 = fmaf(agg3, __ldg(&W2[hB1 * 7 + 0]), pa0);
        pa1 = agg0 * __ldg(&W2[hA0 * 7 + 1]);
        pa1 = fmaf(agg1, __ldg(&W2[hA1 * 7 + 1]), pa1);
        pa1 = fmaf(agg2, __ldg(&W2[hB0 * 7 + 1]), pa1);
        pa1 = fmaf(agg3, __ldg(&W2[hB1 * 7 + 1]), pa1);
        #pragma unroll
        for (int sh = 16; sh > 0; sh >>= 1) {
            pa0 += __shfl_xor_sync(FULL, pa0, sh);
            pa1 += __shfl_xor_sync(FULL, pa1, sh);
        }
        o0 = pa0 + __ldg(&b2[0]);
        o1 = pa1 + __ldg(&b2[1]);
    }

    // ===================== Phase 4: scalar epilogue ==========================
    if (lane == 0) {
        const float* xi = x + (size_t)grow * CC;
        const float vx = xi[2], vy = xi[3];
        float nvx = vx, nvy = vy, npx = pix, npy = piy;

        if (is_cell) {
            float ax = tanhf(o0) * ACC_SCALEF;
            float ay = tanhf(o1) * ACC_SCALEF;
            float ux = vx + ax, uy = vy + ay;
            float sp = sqrtf(ux * ux + uy * uy);
            float sc = fminf(1.0f, MAX_VELF / (sp + 1e-12f));
            ux *= sc; uy *= sc;
            npx = pix + ux; npx -= floorf(npx);
            npy = piy + uy; npy -= floorf(npy);
            const float* nu = noise_u + (size_t)grow * 3;
            const float u0 = nu[0], u1 = nu[1], u2 = nu[2];
            const float nm = (u2 > 0.5f) ? 1.0f : 0.0f;
            nvx = ux + (u0 * 2.0f - 1.0f) * NOISEF * nm;
            nvy = uy + (u1 * 2.0f - 1.0f) * NOISEF * nm;
        }

        const bool dead     =  is_cell && (deg_cell < 1);
        const bool consumed = !is_cell && (deg_cell >= 1);
        const float keep = (dead || consumed) ? 0.0f : 1.0f;

        float* o = out + (size_t)grow * CC;
        o[0] = npx * keep; o[1] = npy * keep;
        o[2] = nvx * keep; o[3] = nvy * keep;
        o[4] = xi[4] * keep;
        o[5] = xi[5] * keep;
        o[6] = xi[6] * keep;
        o[7] = xi[7] * keep;
        o[8] = xi[8] * keep;
        o[9] = xi[9] * keep;
    }
}

// ---------------------------------------------------------------------------
extern "C" void kernel_launch(void* const* d_in, const int* in_sizes, int n_in,
                              void* d_out, int out_size)
{
    const float* x       = (const float*)d_in[0];
    const float* W1      = (const float*)d_in[1];
    const float* b1      = (const float*)d_in[2];
    const float* W2      = (const float*)d_in[3];
    const float* b2      = (const float*)d_in[4];
    const float* noise_u = (const float*)d_in[5];
    float* out = (float*)d_out;

    build_grid_kernel<<<BB, TPB_G>>>(x);
    fused_kernel<<<(BB * MM) / NPW, 256>>>(x, W1, b1, W2, b2, noise_u, out);
}

// round 8
// speedup vs baseline: 1.1289x; 1.1289x over previous
#include <cuda_runtime.h>
#include <math.h>

#define BB 8
#define MM 3072
#define CC 10
#define HH 128
#define KK 32
#define GG 24                 // grid cells per axis; 1/24 > 0.04 radius
#define NCELL (GG * GG)       // 576
#define CAP 48                // per-particle candidate-hit capacity (lambda~15)
#define NPW 8                 // particles (=warps) per 256-thread block
#define FROW 28               // feature row stride in floats (112B, conflict-free STS.128)
#define RADIUSF 0.04f
#define ACC_SCALEF 0.02f
#define MAX_VELF 0.02f
#define NOISEF 0.002f

typedef unsigned long long ull;

// Scratch (no cudaMalloc allowed)
__device__ float4 g_sorted[BB * MM];            // {x, y, id_as_float_bits, pad}
__device__ int    g_cell_off[BB * (NCELL + 1)]; // exclusive offsets per batch

__device__ __forceinline__ int cell_of(float p) {
    int c = (int)(p * (float)GG);
    return c > GG - 1 ? GG - 1 : c;
}

// ---- f32x2 packed helpers (sm_100+) ---------------------------------------
__device__ __forceinline__ ull pack2(float lo, float hi) {
    ull d; asm("mov.b64 %0, {%1, %2};" : "=l"(d) : "f"(lo), "f"(hi)); return d;
}
__device__ __forceinline__ void unpack2(ull v, float &lo, float &hi) {
    asm("mov.b64 {%0, %1}, %2;" : "=f"(lo), "=f"(hi) : "l"(v));
}
__device__ __forceinline__ ull fma2(ull a, ull b, ull c) {
    ull d; asm("fma.rn.f32x2 %0, %1, %2, %3;" : "=l"(d) : "l"(a), "l"(b), "l"(c));
    return d;
}
__device__ __forceinline__ ull add2(ull a, ull b) {
    ull d; asm("add.rn.f32x2 %0, %1, %2;" : "=l"(d) : "l"(a), "l"(b));
    return d;
}
__device__ __forceinline__ void lds2x64(ull &a, ull &b, unsigned addr) {
    asm volatile("ld.shared.v2.b64 {%0, %1}, [%2];" : "=l"(a), "=l"(b) : "r"(addr));
}
__device__ __forceinline__ void lds64(ull &a, unsigned addr) {
    asm volatile("ld.shared.b64 %0, [%1];" : "=l"(a) : "r"(addr));
}
__device__ __forceinline__ unsigned smem_u32(const void* p) {
    return (unsigned)__cvta_generic_to_shared(p);
}

// ---------------------------------------------------------------------------
// Kernel 0: build cell-sorted particle list. One block per batch.
// ---------------------------------------------------------------------------
#define TPB_G 1024
__global__ void __launch_bounds__(TPB_G) build_grid_kernel(const float* __restrict__ x)
{
    __shared__ int s_cnt[NCELL];
    __shared__ int s_wsum[TPB_G / 32];
    __shared__ int s_cur[NCELL];

    const int b = blockIdx.x;
    const int tid = threadIdx.x;
    const int wid = tid >> 5, lane = tid & 31;
    const unsigned FULL = 0xffffffffu;
    const float* xb = x + (size_t)b * MM * CC;

    if (tid < NCELL) s_cnt[tid] = 0;
    __syncthreads();

    int   myc[MM / TPB_G];
    float mpx[MM / TPB_G], mpy[MM / TPB_G];
    #pragma unroll
    for (int r = 0; r < MM / TPB_G; r++) {
        const int i = tid + r * TPB_G;
        const float px = xb[(size_t)i * CC + 0];
        const float py = xb[(size_t)i * CC + 1];
        const int c = cell_of(py) * GG + cell_of(px);
        myc[r] = c; mpx[r] = px; mpy[r] = py;
        atomicAdd(&s_cnt[c], 1);
    }
    __syncthreads();

    // hierarchical exclusive scan over NCELL=576
    int val = (tid < NCELL) ? s_cnt[tid] : 0;
    int incl = val;
    #pragma unroll
    for (int o = 1; o < 32; o <<= 1) {
        int v = __shfl_up_sync(FULL, incl, o);
        if (lane >= o) incl += v;
    }
    if (lane == 31) s_wsum[wid] = incl;
    __syncthreads();
    if (wid == 0) {
        int wv = (lane < TPB_G / 32) ? s_wsum[lane] : 0;
        int wi = wv;
        #pragma unroll
        for (int o = 1; o < 32; o <<= 1) {
            int v = __shfl_up_sync(FULL, wi, o);
            if (lane >= o) wi += v;
        }
        if (lane < TPB_G / 32) s_wsum[lane] = wi - wv;
    }
    __syncthreads();
    if (tid < NCELL) {
        const int excl = s_wsum[wid] + incl - val;
        s_cur[tid] = excl;
        g_cell_off[b * (NCELL + 1) + tid] = excl;
    }
    if (tid == 0) g_cell_off[b * (NCELL + 1) + NCELL] = MM;
    __syncthreads();

    #pragma unroll
    for (int r = 0; r < MM / TPB_G; r++) {
        const int i = tid + r * TPB_G;
        const int slot = atomicAdd(&s_cur[myc[r]], 1);
        g_sorted[(size_t)b * MM + slot] =
            make_float4(mpx[r], mpy[r], __int_as_float(i), 0.0f);
    }
}

// ---------------------------------------------------------------------------
// Fused kernel: one warp per particle. Lane L handles hidden units
// 4L..4L+3 (consecutive) so W1/b1 load as LDG.128. Packed f32x2 MLP,
// exact packed relu via (x+|x|)*0.5.
// ---------------------------------------------------------------------------
__global__ void __launch_bounds__(256, 4) fused_kernel(
    const float* __restrict__ x,  const float* __restrict__ W1,
    const float* __restrict__ b1, const float* __restrict__ W2,
    const float* __restrict__ b2, const float* __restrict__ noise_u,
    float* __restrict__ out)
{
    __shared__ float s_cdx[NPW][CAP], s_cdy[NPW][CAP], s_cds[NPW][CAP];
    __shared__ int   s_cj [NPW][CAP];
    __shared__ __align__(16) float s_feat[NPW][KK * FROW];
    __shared__ int   s_astart[NPW][9];
    __shared__ int   s_bound [NPW][10];

    const unsigned FULL = 0xffffffffu;
    const int warp = threadIdx.x >> 5;
    const int lane = threadIdx.x & 31;
    const int p = warp;
    const int s = blockIdx.x * NPW + p;          // global sorted slot
    const int b = s / MM;
    const int myslot = s - b * MM;

    const float4 me = g_sorted[s];
    const float pix = me.x, piy = me.y;
    const int   myid = __float_as_int(me.z);
    const int   grow = b * MM + myid;

    // ======================= Phase 1: search =================================
    const int cix = cell_of(pix);
    const int ciy = cell_of(piy);
    int len = 0, t0 = 0;
    if (lane < 9) {
        int cy = ciy + (lane / 3) - 1; if (cy < 0) cy += GG; if (cy >= GG) cy -= GG;
        int cx = cix + (lane % 3) - 1; if (cx < 0) cx += GG; if (cx >= GG) cx -= GG;
        const int c = cy * GG + cx;
        t0  = g_cell_off[b * (NCELL + 1) + c];
        len = g_cell_off[b * (NCELL + 1) + c + 1] - t0;
    }
    int incl = len;
    #pragma unroll
    for (int o = 1; o < 16; o <<= 1) {
        int v = __shfl_up_sync(FULL, incl, o);
        if (lane >= o) incl += v;
    }
    const int T = __shfl_sync(FULL, incl, 8);
    if (lane < 9) {
        const int excl = incl - len;
        s_astart[p][lane] = t0 - excl;
        s_bound [p][lane] = excl;
    }
    __syncwarp();

    const float4* __restrict__ sb = g_sorted + (size_t)b * MM;
    int hits = 0;
    for (int base = 0; base < T; base += 32) {
        const int k = base + lane;
        bool pred = false;
        int  cid = 0;
        float dx = 0.f, dy = 0.f, dist = 0.f;
        if (k < T) {
            int q = 0;
            #pragma unroll
            for (int t = 1; t < 9; t++)
                if (k >= s_bound[p][t]) q = t;
            const int tslot = s_astart[p][q] + k;
            const float4 cand = __ldg(&sb[tslot]);
            dx = pix - cand.x; dx -= rintf(dx);
            dy = piy - cand.y; dy -= rintf(dy);
            dist = sqrtf(dx * dx + dy * dy + 1e-12f);
            pred = (dist < RADIUSF) && (tslot != myslot);
            cid = __float_as_int(cand.z);
        }
        const unsigned m = __ballot_sync(FULL, pred);
        if (pred) {
            const int pos = hits + __popc(m & ((1u << lane) - 1));
            if (pos < CAP) {
                s_cj [p][pos] = cid;
                s_cdx[p][pos] = dx;
                s_cdy[p][pos] = dy;
                s_cds[p][pos] = dist;
            }
        }
        hits += __popc(m);
    }
    if (hits > CAP) hits = CAP;
    __syncwarp();

    // rare: rank-select KK nearest, staged through s_feat (edge order is dead:
    // the reference sums over edges)
    if (hits > KK) {
        float* stage = &s_feat[p][0];
        int*   stagei = (int*)&s_feat[p][3 * KK];
        for (int h = lane; h < hits; h += 32) {
            const float dh = s_cds[p][h];
            int rank = 0;
            for (int g2 = 0; g2 < hits; g2++) {
                const float dg = s_cds[p][g2];
                rank += (dg < dh) || (dg == dh && g2 < h);
            }
            if (rank < KK) {
                stage[rank]          = s_cdx[p][h];
                stage[KK + rank]     = s_cdy[p][h];
                stage[2 * KK + rank] = dh;
                stagei[rank]         = s_cj[p][h];
            }
        }
        __syncwarp();
        if (lane < KK) {
            s_cdx[p][lane] = stage[lane];
            s_cdy[p][lane] = stage[KK + lane];
            s_cds[p][lane] = stage[2 * KK + lane];
            s_cj [p][lane] = stagei[lane];
        }
        hits = KK;
        __syncwarp();
    }
    const int cnt = hits;

    const bool is_cell = (__ldg(&x[(size_t)grow * CC + 4]) == 1.0f);

    // ============== Phase 2: gather features (lane = edge) ===================
    float c4v = 0.0f;
    if (lane < cnt) {
        const int j = s_cj[p][lane];
        const float2* xp = (const float2*)(x + ((size_t)b * MM + j) * CC);
        const float2 a2 = __ldg(&xp[2]);    // cell, rest0
        c4v = a2.x;
        if (is_cell) {
            const float2 a1 = __ldg(&xp[1]);
            const float2 a3 = __ldg(&xp[3]);
            const float2 a4 = __ldg(&xp[4]);
            float4* row = (float4*)&s_feat[p][lane * FROW];
            const float ds = s_cds[p][lane];
            const float dx = s_cdx[p][lane];
            const float dy = s_cdy[p][lane];
            row[0] = make_float4(a1.x, a1.x, a1.y, a1.y);  // f0,f0,f1,f1
            row[1] = make_float4(a2.x, a2.x, a2.y, a2.y);  // f2,f2,f3,f3
            row[2] = make_float4(a3.x, a3.x, a3.y, a3.y);  // f4,f4,f5,f5
            row[3] = make_float4(a4.x, a4.x, a4.y, a4.y);  // f6,f6,f7,f7
            row[4] = make_float4(ds,   ds,   dx,   dx);    // f8,f8,f9,f9
            row[5] = make_float4(dy,   dy,   0.f,  0.f);   // f10,f10,pad
        }
    }
    const int deg_cell = __popc(__ballot_sync(FULL, (lane < cnt) && (c4v == 1.0f)));
    __syncwarp();

    // ===================== Phase 3: edge MLP (packed) ========================
    float o0 = 0.0f, o1 = 0.0f;

    if (is_cell) {
        // lane handles hidden units 4*lane .. 4*lane+3 (consecutive -> LDG.128)
        float agg0 = 0.f, agg1 = 0.f, agg2 = 0.f, agg3 = 0.f;
        const int h0 = 4 * lane;

        if (cnt > 0) {
            ull wA[11], wB[11];
            {
                const float4* __restrict__ w11v =
                    (const float4*)(W1 + 11 * HH);
                const float4 wf11 = __ldg(&w11v[lane]);
                #pragma unroll
                for (int f = 0; f < 11; f++) {
                    float4 wf = __ldg(&((const float4*)(W1 + f * HH))[lane]);
                    if (f == 2) {   // fold duplicated feature: msg[11] == msg[2]
                        wf.x += wf11.x; wf.y += wf11.y;
                        wf.z += wf11.z; wf.w += wf11.w;
                    }
                    wA[f] = pack2(wf.x, wf.y);
                    wB[f] = pack2(wf.z, wf.w);
                }
            }
            const float4 bv = __ldg(&((const float4*)b1)[lane]);
            const ull bA = pack2(bv.x, bv.y);
            const ull bB = pack2(bv.z, bv.w);
            const ull HALF2 = pack2(0.5f, 0.5f);
            const ull ABSM  = 0x7fffffff7fffffffULL;
            ull aggA = pack2(0.f, 0.f), aggB = pack2(0.f, 0.f);

            unsigned raddr = smem_u32(&s_feat[p][0]);
            for (int e = 0; e < cnt; e++, raddr += FROW * 4) {
                ull q0, q1, q2, q3;
                ull tA = bA, tB = bB;
                lds2x64(q0, q1, raddr);          // f0, f1
                lds2x64(q2, q3, raddr + 16);     // f2, f3
                tA = fma2(q0, wA[0], tA);  tB = fma2(q0, wB[0], tB);
                tA = fma2(q1, wA[1], tA);  tB = fma2(q1, wB[1], tB);
                lds2x64(q0, q1, raddr + 32);     // f4, f5
                tA = fma2(q2, wA[2], tA);  tB = fma2(q2, wB[2], tB);
                tA = fma2(q3, wA[3], tA);  tB = fma2(q3, wB[3], tB);
                lds2x64(q2, q3, raddr + 48);     // f6, f7
                tA = fma2(q0, wA[4], tA);  tB = fma2(q0, wB[4], tB);
                tA = fma2(q1, wA[5], tA);  tB = fma2(q1, wB[5], tB);
                lds2x64(q0, q1, raddr + 64);     // f8, f9
                tA = fma2(q2, wA[6], tA);  tB = fma2(q2, wB[6], tB);
                tA = fma2(q3, wA[7], tA);  tB = fma2(q3, wB[7], tB);
                lds64(q2, raddr + 80);           // f10
                tA = fma2(q0, wA[8], tA);  tB = fma2(q0, wB[8], tB);
                tA = fma2(q1, wA[9], tA);  tB = fma2(q1, wB[9], tB);
                tA = fma2(q2, wA[10], tA); tB = fma2(q2, wB[10], tB);

                // exact packed relu-accumulate: relu(x) = (x + |x|) * 0.5
                const ull sA = add2(tA, tA & ABSM);
                const ull sB = add2(tB, tB & ABSM);
                aggA = fma2(sA, HALF2, aggA);
                aggB = fma2(sB, HALF2, aggB);
            }
            unpack2(aggA, agg0, agg1);
            unpack2(aggB, agg2, agg3);
        }

        // agg @ W2[:, 0:2]  (outputs 2..6 are dead code in the reference)
        float pa0, pa1;
        pa0 = agg0 * __ldg(&W2[(h0 + 0) * 7 + 0]);
        pa0 = fmaf(agg1, __ldg(&W2[(h0 + 1) * 7 + 0]), pa0);
        pa0 = fmaf(agg2, __ldg(&W2[(h0 + 2) * 7 + 0]), pa0);
        pa0 = fmaf(agg3, __ldg(&W2[(h0 + 3) * 7 + 0]), pa0);
        pa1 = agg0 * __ldg(&W2[(h0 + 0) * 7 + 1]);
        pa1 = fmaf(agg1, __ldg(&W2[(h0 + 1) * 7 + 1]), pa1);
        pa1 = fmaf(agg2, __ldg(&W2[(h0 + 2) * 7 + 1]), pa1);
        pa1 = fmaf(agg3, __ldg(&W2[(h0 + 3) * 7 + 1]), pa1);
        #pragma unroll
        for (int sh = 16; sh > 0; sh >>= 1) {
            pa0 += __shfl_xor_sync(FULL, pa0, sh);
            pa1 += __shfl_xor_sync(FULL, pa1, sh);
        }
        o0 = pa0 + __ldg(&b2[0]);
        o1 = pa1 + __ldg(&b2[1]);
    }

    // ===================== Phase 4: scalar epilogue ==========================
    if (lane == 0) {
        const float* xi = x + (size_t)grow * CC;
        const float vx = xi[2], vy = xi[3];
        float nvx = vx, nvy = vy, npx = pix, npy = piy;

        if (is_cell) {
            float ax = tanhf(o0) * ACC_SCALEF;
            float ay = tanhf(o1) * ACC_SCALEF;
            float ux = vx + ax, uy = vy + ay;
            float sp = sqrtf(ux * ux + uy * uy);
            float sc = fminf(1.0f, MAX_VELF / (sp + 1e-12f));
            ux *= sc; uy *= sc;
            npx = pix + ux; npx -= floorf(npx);
            npy = piy + uy; npy -= floorf(npy);
            const float* nu = noise_u + (size_t)grow * 3;
            const float u0 = nu[0], u1 = nu[1], u2 = nu[2];
            const float nm = (u2 > 0.5f) ? 1.0f : 0.0f;
            nvx = ux + (u0 * 2.0f - 1.0f) * NOISEF * nm;
            nvy = uy + (u1 * 2.0f - 1.0f) * NOISEF * nm;
        }

        const bool dead     =  is_cell && (deg_cell < 1);
        const bool consumed = !is_cell && (deg_cell >= 1);
        const float keep = (dead || consumed) ? 0.0f : 1.0f;

        float* o = out + (size_t)grow * CC;
        o[0] = npx * keep; o[1] = npy * keep;
        o[2] = nvx * keep; o[3] = nvy * keep;
        o[4] = xi[4] * keep;
        o[5] = xi[5] * keep;
        o[6] = xi[6] * keep;
        o[7] = xi[7] * keep;
        o[8] = xi[8] * keep;
        o[9] = xi[9] * keep;
    }
}

// ---------------------------------------------------------------------------
extern "C" void kernel_launch(void* const* d_in, const int* in_sizes, int n_in,
                              void* d_out, int out_size)
{
    const float* x       = (const float*)d_in[0];
    const float* W1      = (const float*)d_in[1];
    const float* b1      = (const float*)d_in[2];
    const float* W2      = (const float*)d_in[3];
    const float* b2      = (const float*)d_in[4];
    const float* noise_u = (const float*)d_in[5];
    float* out = (float*)d_out;

    build_grid_kernel<<<BB, TPB_G>>>(x);
    fused_kernel<<<(BB * MM) / NPW, 256>>>(x, W1, b1, W2, b2, noise_u, out);
}

// round 9
// speedup vs baseline: 1.2021x; 1.0649x over previous
#include <cuda_runtime.h>
#include <math.h>

#define BB 8
#define MM 3072
#define CC 10
#define HH 128
#define KK 32
#define GG 24                 // grid cells per axis; 1/24 > 0.04 radius
#define NCELL (GG * GG)       // 576
#define CAP 48                // per-particle candidate-hit capacity (lambda~15)
#define NPW 8                 // particles (=warps) per 256-thread block
#define FROW 28               // feature row stride in floats (112B, conflict-free STS.128)
#define RADIUSF 0.04f
#define ACC_SCALEF 0.02f
#define MAX_VELF 0.02f
#define NOISEF 0.002f

typedef unsigned long long ull;

// Scratch (no cudaMalloc allowed)
__device__ float4 g_sorted[BB * MM];            // {x, y, id_as_float_bits, pad}
__device__ int    g_cell_off[BB * (NCELL + 1)]; // exclusive offsets per batch

__device__ __forceinline__ int cell_of(float p) {
    int c = (int)(p * (float)GG);
    return c > GG - 1 ? GG - 1 : c;
}

// ---- f32x2 packed helpers (sm_100+) ---------------------------------------
__device__ __forceinline__ ull pack2(float lo, float hi) {
    ull d; asm("mov.b64 %0, {%1, %2};" : "=l"(d) : "f"(lo), "f"(hi)); return d;
}
__device__ __forceinline__ void unpack2(ull v, float &lo, float &hi) {
    asm("mov.b64 {%0, %1}, %2;" : "=f"(lo), "=f"(hi) : "l"(v));
}
__device__ __forceinline__ ull fma2(ull a, ull b, ull c) {
    ull d; asm("fma.rn.f32x2 %0, %1, %2, %3;" : "=l"(d) : "l"(a), "l"(b), "l"(c));
    return d;
}
__device__ __forceinline__ ull add2(ull a, ull b) {
    ull d; asm("add.rn.f32x2 %0, %1, %2;" : "=l"(d) : "l"(a), "l"(b));
    return d;
}
__device__ __forceinline__ void lds2x64(ull &a, ull &b, unsigned addr) {
    asm volatile("ld.shared.v2.b64 {%0, %1}, [%2];" : "=l"(a), "=l"(b) : "r"(addr));
}
__device__ __forceinline__ void lds64(ull &a, unsigned addr) {
    asm volatile("ld.shared.b64 %0, [%1];" : "=l"(a) : "r"(addr));
}
__device__ __forceinline__ unsigned smem_u32(const void* p) {
    return (unsigned)__cvta_generic_to_shared(p);
}

// ---------------------------------------------------------------------------
// Kernel 0: build cell-sorted particle list. One block per batch.
// ---------------------------------------------------------------------------
#define TPB_G 1024
__global__ void __launch_bounds__(TPB_G) build_grid_kernel(const float* __restrict__ x)
{
    __shared__ int s_cnt[NCELL];
    __shared__ int s_wsum[TPB_G / 32];
    __shared__ int s_cur[NCELL];

    const int b = blockIdx.x;
    const int tid = threadIdx.x;
    const int wid = tid >> 5, lane = tid & 31;
    const unsigned FULL = 0xffffffffu;
    const float* xb = x + (size_t)b * MM * CC;

    if (tid < NCELL) s_cnt[tid] = 0;
    __syncthreads();

    int   myc[MM / TPB_G];
    float mpx[MM / TPB_G], mpy[MM / TPB_G];
    #pragma unroll
    for (int r = 0; r < MM / TPB_G; r++) {
        const int i = tid + r * TPB_G;
        const float px = xb[(size_t)i * CC + 0];
        const float py = xb[(size_t)i * CC + 1];
        const int c = cell_of(py) * GG + cell_of(px);
        myc[r] = c; mpx[r] = px; mpy[r] = py;
        atomicAdd(&s_cnt[c], 1);
    }
    __syncthreads();

    // hierarchical exclusive scan over NCELL=576
    int val = (tid < NCELL) ? s_cnt[tid] : 0;
    int incl = val;
    #pragma unroll
    for (int o = 1; o < 32; o <<= 1) {
        int v = __shfl_up_sync(FULL, incl, o);
        if (lane >= o) incl += v;
    }
    if (lane == 31) s_wsum[wid] = incl;
    __syncthreads();
    if (wid == 0) {
        int wv = (lane < TPB_G / 32) ? s_wsum[lane] : 0;
        int wi = wv;
        #pragma unroll
        for (int o = 1; o < 32; o <<= 1) {
            int v = __shfl_up_sync(FULL, wi, o);
            if (lane >= o) wi += v;
        }
        if (lane < TPB_G / 32) s_wsum[lane] = wi - wv;
    }
    __syncthreads();
    if (tid < NCELL) {
        const int excl = s_wsum[wid] + incl - val;
        s_cur[tid] = excl;
        g_cell_off[b * (NCELL + 1) + tid] = excl;
    }
    if (tid == 0) g_cell_off[b * (NCELL + 1) + NCELL] = MM;
    __syncthreads();

    #pragma unroll
    for (int r = 0; r < MM / TPB_G; r++) {
        const int i = tid + r * TPB_G;
        const int slot = atomicAdd(&s_cur[myc[r]], 1);
        g_sorted[(size_t)b * MM + slot] =
            make_float4(mpx[r], mpy[r], __int_as_float(i), 0.0f);
    }
}

// ---------------------------------------------------------------------------
// Fused kernel: one warp per particle. Lane L handles hidden units
// 4L..4L+3 (consecutive) so W1/b1 load as LDG.128. Packed f32x2 MLP,
// exact packed relu via (x+|x|)*0.5. NO tight reg cap (spills cost more
// than occupancy buys: R6-R8 evidence).
// ---------------------------------------------------------------------------
__global__ void __launch_bounds__(256, 3) fused_kernel(
    const float* __restrict__ x,  const float* __restrict__ W1,
    const float* __restrict__ b1, const float* __restrict__ W2,
    const float* __restrict__ b2, const float* __restrict__ noise_u,
    float* __restrict__ out)
{
    __shared__ float s_cdx[NPW][CAP], s_cdy[NPW][CAP], s_cds[NPW][CAP];
    __shared__ int   s_cj [NPW][CAP];
    __shared__ __align__(16) float s_feat[NPW][KK * FROW];
    __shared__ int   s_astart[NPW][9];
    __shared__ int   s_bound [NPW][10];

    const unsigned FULL = 0xffffffffu;
    const int warp = threadIdx.x >> 5;
    const int lane = threadIdx.x & 31;
    const int p = warp;
    const int s = blockIdx.x * NPW + p;          // global sorted slot
    const int b = s / MM;
    const int myslot = s - b * MM;

    const float4 me = g_sorted[s];
    const float pix = me.x, piy = me.y;
    const int   myid = __float_as_int(me.z);
    const int   grow = b * MM + myid;

    // ======================= Phase 1: search =================================
    const int cix = cell_of(pix);
    const int ciy = cell_of(piy);
    int len = 0, t0 = 0;
    if (lane < 9) {
        int cy = ciy + (lane / 3) - 1; if (cy < 0) cy += GG; if (cy >= GG) cy -= GG;
        int cx = cix + (lane % 3) - 1; if (cx < 0) cx += GG; if (cx >= GG) cx -= GG;
        const int c = cy * GG + cx;
        t0  = g_cell_off[b * (NCELL + 1) + c];
        len = g_cell_off[b * (NCELL + 1) + c + 1] - t0;
    }
    int incl = len;
    #pragma unroll
    for (int o = 1; o < 16; o <<= 1) {
        int v = __shfl_up_sync(FULL, incl, o);
        if (lane >= o) incl += v;
    }
    const int T = __shfl_sync(FULL, incl, 8);
    if (lane < 9) {
        const int excl = incl - len;
        s_astart[p][lane] = t0 - excl;
        s_bound [p][lane] = excl;
    }
    __syncwarp();

    const float4* __restrict__ sb = g_sorted + (size_t)b * MM;
    int hits = 0;
    for (int base = 0; base < T; base += 32) {
        const int k = base + lane;
        bool pred = false;
        int  cid = 0;
        float dx = 0.f, dy = 0.f, dist = 0.f;
        if (k < T) {
            int q = 0;
            #pragma unroll
            for (int t = 1; t < 9; t++)
                if (k >= s_bound[p][t]) q = t;
            const int tslot = s_astart[p][q] + k;
            const float4 cand = __ldg(&sb[tslot]);
            dx = pix - cand.x; dx -= rintf(dx);
            dy = piy - cand.y; dy -= rintf(dy);
            dist = sqrtf(dx * dx + dy * dy + 1e-12f);
            pred = (dist < RADIUSF) && (tslot != myslot);
            cid = __float_as_int(cand.z);
        }
        const unsigned m = __ballot_sync(FULL, pred);
        if (pred) {
            const int pos = hits + __popc(m & ((1u << lane) - 1));
            if (pos < CAP) {
                s_cj [p][pos] = cid;
                s_cdx[p][pos] = dx;
                s_cdy[p][pos] = dy;
                s_cds[p][pos] = dist;
            }
        }
        hits += __popc(m);
    }
    if (hits > CAP) hits = CAP;
    __syncwarp();

    // rare: rank-select KK nearest, staged through s_feat (edge order is dead:
    // the reference sums over edges)
    if (hits > KK) {
        float* stage = &s_feat[p][0];
        int*   stagei = (int*)&s_feat[p][3 * KK];
        for (int h = lane; h < hits; h += 32) {
            const float dh = s_cds[p][h];
            int rank = 0;
            for (int g2 = 0; g2 < hits; g2++) {
                const float dg = s_cds[p][g2];
                rank += (dg < dh) || (dg == dh && g2 < h);
            }
            if (rank < KK) {
                stage[rank]          = s_cdx[p][h];
                stage[KK + rank]     = s_cdy[p][h];
                stage[2 * KK + rank] = dh;
                stagei[rank]         = s_cj[p][h];
            }
        }
        __syncwarp();
        if (lane < KK) {
            s_cdx[p][lane] = stage[lane];
            s_cdy[p][lane] = stage[KK + lane];
            s_cds[p][lane] = stage[2 * KK + lane];
            s_cj [p][lane] = stagei[lane];
        }
        hits = KK;
        __syncwarp();
    }
    const int cnt = hits;

    const bool is_cell = (__ldg(&x[(size_t)grow * CC + 4]) == 1.0f);

    // ============== Phase 2: gather features (lane = edge) ===================
    float c4v = 0.0f;
    if (lane < cnt) {
        const int j = s_cj[p][lane];
        const float2* xp = (const float2*)(x + ((size_t)b * MM + j) * CC);
        const float2 a2 = __ldg(&xp[2]);    // cell, rest0
        c4v = a2.x;
        if (is_cell) {
            const float2 a1 = __ldg(&xp[1]);
            const float2 a3 = __ldg(&xp[3]);
            const float2 a4 = __ldg(&xp[4]);
            float4* row = (float4*)&s_feat[p][lane * FROW];
            const float ds = s_cds[p][lane];
            const float dx = s_cdx[p][lane];
            const float dy = s_cdy[p][lane];
            row[0] = make_float4(a1.x, a1.x, a1.y, a1.y);  // f0,f0,f1,f1
            row[1] = make_float4(a2.x, a2.x, a2.y, a2.y);  // f2,f2,f3,f3
            row[2] = make_float4(a3.x, a3.x, a3.y, a3.y);  // f4,f4,f5,f5
            row[3] = make_float4(a4.x, a4.x, a4.y, a4.y);  // f6,f6,f7,f7
            row[4] = make_float4(ds,   ds,   dx,   dx);    // f8,f8,f9,f9
            row[5] = make_float4(dy,   dy,   0.f,  0.f);   // f10,f10,pad
        }
    }
    const int deg_cell = __popc(__ballot_sync(FULL, (lane < cnt) && (c4v == 1.0f)));
    __syncwarp();

    // ===================== Phase 3: edge MLP (packed) ========================
    float o0 = 0.0f, o1 = 0.0f;

    if (is_cell) {
        // lane handles hidden units 4*lane .. 4*lane+3 (consecutive -> LDG.128)
        float agg0 = 0.f, agg1 = 0.f, agg2 = 0.f, agg3 = 0.f;
        const int h0 = 4 * lane;

        if (cnt > 0) {
            ull wA[11], wB[11];
            {
                const float4* __restrict__ w11v =
                    (const float4*)(W1 + 11 * HH);
                const float4 wf11 = __ldg(&w11v[lane]);
                #pragma unroll
                for (int f = 0; f < 11; f++) {
                    float4 wf = __ldg(&((const float4*)(W1 + f * HH))[lane]);
                    if (f == 2) {   // fold duplicated feature: msg[11] == msg[2]
                        wf.x += wf11.x; wf.y += wf11.y;
                        wf.z += wf11.z; wf.w += wf11.w;
                    }
                    wA[f] = pack2(wf.x, wf.y);
                    wB[f] = pack2(wf.z, wf.w);
                }
            }
            const float4 bv = __ldg(&((const float4*)b1)[lane]);
            const ull bA = pack2(bv.x, bv.y);
            const ull bB = pack2(bv.z, bv.w);
            const ull HALF2 = pack2(0.5f, 0.5f);
            const ull ABSM  = 0x7fffffff7fffffffULL;
            ull aggA = pack2(0.f, 0.f), aggB = pack2(0.f, 0.f);

            unsigned raddr = smem_u32(&s_feat[p][0]);
            for (int e = 0; e < cnt; e++, raddr += FROW * 4) {
                ull q0, q1, q2, q3;
                ull tA = bA, tB = bB;
                lds2x64(q0, q1, raddr);          // f0, f1
                lds2x64(q2, q3, raddr + 16);     // f2, f3
                tA = fma2(q0, wA[0], tA);  tB = fma2(q0, wB[0], tB);
                tA = fma2(q1, wA[1], tA);  tB = fma2(q1, wB[1], tB);
                lds2x64(q0, q1, raddr + 32);     // f4, f5
                tA = fma2(q2, wA[2], tA);  tB = fma2(q2, wB[2], tB);
                tA = fma2(q3, wA[3], tA);  tB = fma2(q3, wB[3], tB);
                lds2x64(q2, q3, raddr + 48);     // f6, f7
                tA = fma2(q0, wA[4], tA);  tB = fma2(q0, wB[4], tB);
                tA = fma2(q1, wA[5], tA);  tB = fma2(q1, wB[5], tB);
                lds2x64(q0, q1, raddr + 64);     // f8, f9
                tA = fma2(q2, wA[6], tA);  tB = fma2(q2, wB[6], tB);
                tA = fma2(q3, wA[7], tA);  tB = fma2(q3, wB[7], tB);
                lds64(q2, raddr + 80);           // f10
                tA = fma2(q0, wA[8], tA);  tB = fma2(q0, wB[8], tB);
                tA = fma2(q1, wA[9], tA);  tB = fma2(q1, wB[9], tB);
                tA = fma2(q2, wA[10], tA); tB = fma2(q2, wB[10], tB);

                // exact packed relu-accumulate: relu(x) = (x + |x|) * 0.5
                const ull sA = add2(tA, tA & ABSM);
                const ull sB = add2(tB, tB & ABSM);
                aggA = fma2(sA, HALF2, aggA);
                aggB = fma2(sB, HALF2, aggB);
            }
            unpack2(aggA, agg0, agg1);
            unpack2(aggB, agg2, agg3);
        }

        // agg @ W2[:, 0:2]  (outputs 2..6 are dead code in the reference)
        float pa0, pa1;
        pa0 = agg0 * __ldg(&W2[(h0 + 0) * 7 + 0]);
        pa0 = fmaf(agg1, __ldg(&W2[(h0 + 1) * 7 + 0]), pa0);
        pa0 = fmaf(agg2, __ldg(&W2[(h0 + 2) * 7 + 0]), pa0);
        pa0 = fmaf(agg3, __ldg(&W2[(h0 + 3) * 7 + 0]), pa0);
        pa1 = agg0 * __ldg(&W2[(h0 + 0) * 7 + 1]);
        pa1 = fmaf(agg1, __ldg(&W2[(h0 + 1) * 7 + 1]), pa1);
        pa1 = fmaf(agg2, __ldg(&W2[(h0 + 2) * 7 + 1]), pa1);
        pa1 = fmaf(agg3, __ldg(&W2[(h0 + 3) * 7 + 1]), pa1);
        #pragma unroll
        for (int sh = 16; sh > 0; sh >>= 1) {
            pa0 += __shfl_xor_sync(FULL, pa0, sh);
            pa1 += __shfl_xor_sync(FULL, pa1, sh);
        }
        o0 = pa0 + __ldg(&b2[0]);
        o1 = pa1 + __ldg(&b2[1]);
    }

    // ===================== Phase 4: scalar epilogue ==========================
    if (lane == 0) {
        const float* xi = x + (size_t)grow * CC;
        const float vx = xi[2], vy = xi[3];
        float nvx = vx, nvy = vy, npx = pix, npy = piy;

        if (is_cell) {
            float ax = tanhf(o0) * ACC_SCALEF;
            float ay = tanhf(o1) * ACC_SCALEF;
            float ux = vx + ax, uy = vy + ay;
            float sp = sqrtf(ux * ux + uy * uy);
            float sc = fminf(1.0f, MAX_VELF / (sp + 1e-12f));
            ux *= sc; uy *= sc;
            npx = pix + ux; npx -= floorf(npx);
            npy = piy + uy; npy -= floorf(npy);
            const float* nu = noise_u + (size_t)grow * 3;
            const float u0 = nu[0], u1 = nu[1], u2 = nu[2];
            const float nm = (u2 > 0.5f) ? 1.0f : 0.0f;
            nvx = ux + (u0 * 2.0f - 1.0f) * NOISEF * nm;
            nvy = uy + (u1 * 2.0f - 1.0f) * NOISEF * nm;
        }

        const bool dead     =  is_cell && (deg_cell < 1);
        const bool consumed = !is_cell && (deg_cell >= 1);
        const float keep = (dead || consumed) ? 0.0f : 1.0f;

        float* o = out + (size_t)grow * CC;
        o[0] = npx * keep; o[1] = npy * keep;
        o[2] = nvx * keep; o[3] = nvy * keep;
        o[4] = xi[4] * keep;
        o[5] = xi[5] * keep;
        o[6] = xi[6] * keep;
        o[7] = xi[7] * keep;
        o[8] = xi[8] * keep;
        o[9] = xi[9] * keep;
    }
}

// ---------------------------------------------------------------------------
extern "C" void kernel_launch(void* const* d_in, const int* in_sizes, int n_in,
                              void* d_out, int out_size)
{
    const float* x       = (const float*)d_in[0];
    const float* W1      = (const float*)d_in[1];
    const float* b1      = (const float*)d_in[2];
    const float* W2      = (const float*)d_in[3];
    const float* b2      = (const float*)d_in[4];
    const float* noise_u = (const float*)d_in[5];
    float* out = (float*)d_out;

    build_grid_kernel<<<BB, TPB_G>>>(x);
    fused_kernel<<<(BB * MM) / NPW, 256>>>(x, W1, b1, W2, b2, noise_u, out);
}

// round 10
// speedup vs baseline: 1.2312x; 1.0242x over previous
#include <cuda_runtime.h>
#include <math.h>

#define BB 8
#define MM 3072
#define CC 10
#define HH 128
#define KK 32
#define GG 24                 // grid cells per axis; 1/24 > 0.04 radius
#define NCELL (GG * GG)       // 576
#define CAP 48                // per-particle candidate-hit capacity (lambda~15)
#define NPW 8                 // particles (=warps) per 256-thread block
#define FROW 28               // feature row stride in floats (112B, conflict-free STS.128)
#define RADIUSF 0.04f
#define ACC_SCALEF 0.02f
#define MAX_VELF 0.02f
#define NOISEF 0.002f

typedef unsigned long long ull;

// Scratch (no cudaMalloc allowed)
__device__ float4 g_sorted[BB * MM];            // {x, y, id_as_float_bits, pad}
__device__ int    g_cell_off[BB * (NCELL + 1)]; // exclusive offsets per batch

__device__ __forceinline__ int cell_of(float p) {
    int c = (int)(p * (float)GG);
    return c > GG - 1 ? GG - 1 : c;
}

// ---- f32x2 packed helpers (sm_100+) ---------------------------------------
__device__ __forceinline__ ull pack2(float lo, float hi) {
    ull d; asm("mov.b64 %0, {%1, %2};" : "=l"(d) : "f"(lo), "f"(hi)); return d;
}
__device__ __forceinline__ void unpack2(ull v, float &lo, float &hi) {
    asm("mov.b64 {%0, %1}, %2;" : "=f"(lo), "=f"(hi) : "l"(v));
}
__device__ __forceinline__ ull fma2(ull a, ull b, ull c) {
    ull d; asm("fma.rn.f32x2 %0, %1, %2, %3;" : "=l"(d) : "l"(a), "l"(b), "l"(c));
    return d;
}
__device__ __forceinline__ ull add2(ull a, ull b) {
    ull d; asm("add.rn.f32x2 %0, %1, %2;" : "=l"(d) : "l"(a), "l"(b));
    return d;
}
__device__ __forceinline__ void lds2x64(ull &a, ull &b, unsigned addr) {
    asm volatile("ld.shared.v2.b64 {%0, %1}, [%2];" : "=l"(a), "=l"(b) : "r"(addr));
}
__device__ __forceinline__ void lds64(ull &a, unsigned addr) {
    asm volatile("ld.shared.b64 %0, [%1];" : "=l"(a) : "r"(addr));
}
__device__ __forceinline__ unsigned smem_u32(const void* p) {
    return (unsigned)__cvta_generic_to_shared(p);
}

// ---------------------------------------------------------------------------
// Kernel 0: build cell-sorted particle list. One block per batch.
// ---------------------------------------------------------------------------
#define TPB_G 1024
__global__ void __launch_bounds__(TPB_G) build_grid_kernel(const float* __restrict__ x)
{
    __shared__ int s_cnt[NCELL];
    __shared__ int s_wsum[TPB_G / 32];
    __shared__ int s_cur[NCELL];

    const int b = blockIdx.x;
    const int tid = threadIdx.x;
    const int wid = tid >> 5, lane = tid & 31;
    const unsigned FULL = 0xffffffffu;
    const float* xb = x + (size_t)b * MM * CC;

    if (tid < NCELL) s_cnt[tid] = 0;
    __syncthreads();

    int   myc[MM / TPB_G];
    float mpx[MM / TPB_G], mpy[MM / TPB_G];
    #pragma unroll
    for (int r = 0; r < MM / TPB_G; r++) {
        const int i = tid + r * TPB_G;
        const float px = xb[(size_t)i * CC + 0];
        const float py = xb[(size_t)i * CC + 1];
        const int c = cell_of(py) * GG + cell_of(px);
        myc[r] = c; mpx[r] = px; mpy[r] = py;
        atomicAdd(&s_cnt[c], 1);
    }
    __syncthreads();

    // hierarchical exclusive scan over NCELL=576
    int val = (tid < NCELL) ? s_cnt[tid] : 0;
    int incl = val;
    #pragma unroll
    for (int o = 1; o < 32; o <<= 1) {
        int v = __shfl_up_sync(FULL, incl, o);
        if (lane >= o) incl += v;
    }
    if (lane == 31) s_wsum[wid] = incl;
    __syncthreads();
    if (wid == 0) {
        int wv = (lane < TPB_G / 32) ? s_wsum[lane] : 0;
        int wi = wv;
        #pragma unroll
        for (int o = 1; o < 32; o <<= 1) {
            int v = __shfl_up_sync(FULL, wi, o);
            if (lane >= o) wi += v;
        }
        if (lane < TPB_G / 32) s_wsum[lane] = wi - wv;
    }
    __syncthreads();
    if (tid < NCELL) {
        const int excl = s_wsum[wid] + incl - val;
        s_cur[tid] = excl;
        g_cell_off[b * (NCELL + 1) + tid] = excl;
    }
    if (tid == 0) g_cell_off[b * (NCELL + 1) + NCELL] = MM;
    __syncthreads();

    #pragma unroll
    for (int r = 0; r < MM / TPB_G; r++) {
        const int i = tid + r * TPB_G;
        const int slot = atomicAdd(&s_cur[myc[r]], 1);
        g_sorted[(size_t)b * MM + slot] =
            make_float4(mpx[r], mpy[r], __int_as_float(i), 0.0f);
    }
}

// ---------------------------------------------------------------------------
// Fused kernel: one warp per particle.
//  - early prefetch of own x row + noise (epilogue latency hidden)
//  - both candidate-scan LDG rounds issued together (one round-trip)
//  - MLP identical to R9 (LDG.128 weights, packed f32x2, packed relu)
//  - all-lane epilogue, 10 outputs stored by lanes 0..9 in one STG round
// ---------------------------------------------------------------------------
__global__ void __launch_bounds__(256, 3) fused_kernel(
    const float* __restrict__ x,  const float* __restrict__ W1,
    const float* __restrict__ b1, const float* __restrict__ W2,
    const float* __restrict__ b2, const float* __restrict__ noise_u,
    float* __restrict__ out)
{
    __shared__ float s_cdx[NPW][CAP], s_cdy[NPW][CAP], s_cds[NPW][CAP];
    __shared__ int   s_cj [NPW][CAP];
    __shared__ __align__(16) float s_feat[NPW][KK * FROW];
    __shared__ int   s_astart[NPW][9];
    __shared__ int   s_bound [NPW][10];

    const unsigned FULL = 0xffffffffu;
    const int warp = threadIdx.x >> 5;
    const int lane = threadIdx.x & 31;
    const int p = warp;
    const int s = blockIdx.x * NPW + p;          // global sorted slot
    const int b = s / MM;
    const int myslot = s - b * MM;

    const float4 me = g_sorted[s];
    const float pix = me.x, piy = me.y;
    const int   myid = __float_as_int(me.z);
    const int   grow = b * MM + myid;

    // ---- early prefetch: own row + noise (used ~2000 cycles later) ----------
    const float xv = (lane < CC) ? __ldg(&x[(size_t)grow * CC + lane]) : 0.0f;
    const float nz = (lane < 3)  ? __ldg(&noise_u[(size_t)grow * 3 + lane]) : 0.0f;
    const bool is_cell = (__shfl_sync(FULL, xv, 4) == 1.0f);

    // ======================= Phase 1: search =================================
    const int cix = cell_of(pix);
    const int ciy = cell_of(piy);
    int len = 0, t0 = 0;
    if (lane < 9) {
        int cy = ciy + (lane / 3) - 1; if (cy < 0) cy += GG; if (cy >= GG) cy -= GG;
        int cx = cix + (lane % 3) - 1; if (cx < 0) cx += GG; if (cx >= GG) cx -= GG;
        const int c = cy * GG + cx;
        t0  = g_cell_off[b * (NCELL + 1) + c];
        len = g_cell_off[b * (NCELL + 1) + c + 1] - t0;
    }
    int incl = len;
    #pragma unroll
    for (int o = 1; o < 16; o <<= 1) {
        int v = __shfl_up_sync(FULL, incl, o);
        if (lane >= o) incl += v;
    }
    const int T = __shfl_sync(FULL, incl, 8);
    if (lane < 9) {
        const int excl = incl - len;
        s_astart[p][lane] = t0 - excl;
        s_bound [p][lane] = excl;
    }
    __syncwarp();

    const float4* __restrict__ sb = g_sorted + (size_t)b * MM;

    // slot for candidate index k (bucket search over 9 prefix bounds)
    auto slot_of = [&](int k) -> int {
        int q = 0;
        #pragma unroll
        for (int t = 1; t < 9; t++)
            if (k >= s_bound[p][t]) q = t;
        return s_astart[p][q] + k;
    };

    // prefetch BOTH rounds' candidates (addresses known now -> one round-trip)
    const int k0 = lane, k1 = lane + 32;
    int ts0 = 0, ts1 = 0;
    float4 cand0 = make_float4(0.f, 0.f, 0.f, 0.f);
    float4 cand1 = make_float4(0.f, 0.f, 0.f, 0.f);
    if (k0 < T) { ts0 = slot_of(k0); cand0 = __ldg(&sb[ts0]); }
    if (k1 < T) { ts1 = slot_of(k1); cand1 = __ldg(&sb[ts1]); }

    int hits = 0;
    #pragma unroll
    for (int rnd = 0; rnd < 2; rnd++) {
        const int     k    = rnd ? k1 : k0;
        const int     tslt = rnd ? ts1 : ts0;
        const float4  cand = rnd ? cand1 : cand0;
        bool pred = false;
        float dx = 0.f, dy = 0.f, dist = 0.f;
        if (k < T) {
            dx = pix - cand.x; dx -= rintf(dx);
            dy = piy - cand.y; dy -= rintf(dy);
            dist = sqrtf(dx * dx + dy * dy + 1e-12f);
            pred = (dist < RADIUSF) && (tslt != myslot);
        }
        const unsigned m = __ballot_sync(FULL, pred);
        if (pred) {
            const int pos = hits + __popc(m & ((1u << lane) - 1));
            if (pos < CAP) {
                s_cj [p][pos] = __float_as_int(cand.z);
                s_cdx[p][pos] = dx;
                s_cdy[p][pos] = dy;
                s_cds[p][pos] = dist;
            }
        }
        hits += __popc(m);
    }
    // rare: T > 64
    for (int base = 64; base < T; base += 32) {
        const int k = base + lane;
        bool pred = false;
        int  cid = 0;
        float dx = 0.f, dy = 0.f, dist = 0.f;
        if (k < T) {
            const int tslot = slot_of(k);
            const float4 cand = __ldg(&sb[tslot]);
            dx = pix - cand.x; dx -= rintf(dx);
            dy = piy - cand.y; dy -= rintf(dy);
            dist = sqrtf(dx * dx + dy * dy + 1e-12f);
            pred = (dist < RADIUSF) && (tslot != myslot);
            cid = __float_as_int(cand.z);
        }
        const unsigned m = __ballot_sync(FULL, pred);
        if (pred) {
            const int pos = hits + __popc(m & ((1u << lane) - 1));
            if (pos < CAP) {
                s_cj [p][pos] = cid;
                s_cdx[p][pos] = dx;
                s_cdy[p][pos] = dy;
                s_cds[p][pos] = dist;
            }
        }
        hits += __popc(m);
    }
    if (hits > CAP) hits = CAP;
    __syncwarp();

    // rare: rank-select KK nearest, staged through s_feat (edge order is dead:
    // the reference sums over edges)
    if (hits > KK) {
        float* stage = &s_feat[p][0];
        int*   stagei = (int*)&s_feat[p][3 * KK];
        for (int h = lane; h < hits; h += 32) {
            const float dh = s_cds[p][h];
            int rank = 0;
            for (int g2 = 0; g2 < hits; g2++) {
                const float dg = s_cds[p][g2];
                rank += (dg < dh) || (dg == dh && g2 < h);
            }
            if (rank < KK) {
                stage[rank]          = s_cdx[p][h];
                stage[KK + rank]     = s_cdy[p][h];
                stage[2 * KK + rank] = dh;
                stagei[rank]         = s_cj[p][h];
            }
        }
        __syncwarp();
        if (lane < KK) {
            s_cdx[p][lane] = stage[lane];
            s_cdy[p][lane] = stage[KK + lane];
            s_cds[p][lane] = stage[2 * KK + lane];
            s_cj [p][lane] = stagei[lane];
        }
        hits = KK;
        __syncwarp();
    }
    const int cnt = hits;

    // ============== Phase 2: gather features (lane = edge) ===================
    float c4v = 0.0f;
    if (lane < cnt) {
        const int j = s_cj[p][lane];
        const float2* xp = (const float2*)(x + ((size_t)b * MM + j) * CC);
        const float2 a2 = __ldg(&xp[2]);    // cell, rest0
        c4v = a2.x;
        if (is_cell) {
            const float2 a1 = __ldg(&xp[1]);
            const float2 a3 = __ldg(&xp[3]);
            const float2 a4 = __ldg(&xp[4]);
            float4* row = (float4*)&s_feat[p][lane * FROW];
            const float ds = s_cds[p][lane];
            const float dx = s_cdx[p][lane];
            const float dy = s_cdy[p][lane];
            row[0] = make_float4(a1.x, a1.x, a1.y, a1.y);  // f0,f0,f1,f1
            row[1] = make_float4(a2.x, a2.x, a2.y, a2.y);  // f2,f2,f3,f3
            row[2] = make_float4(a3.x, a3.x, a3.y, a3.y);  // f4,f4,f5,f5
            row[3] = make_float4(a4.x, a4.x, a4.y, a4.y);  // f6,f6,f7,f7
            row[4] = make_float4(ds,   ds,   dx,   dx);    // f8,f8,f9,f9
            row[5] = make_float4(dy,   dy,   0.f,  0.f);   // f10,f10,pad
        }
    }
    const int deg_cell = __popc(__ballot_sync(FULL, (lane < cnt) && (c4v == 1.0f)));
    __syncwarp();

    // ===================== Phase 3: edge MLP (packed) ========================
    float o0 = 0.0f, o1 = 0.0f;

    if (is_cell) {
        // lane handles hidden units 4*lane .. 4*lane+3 (consecutive -> LDG.128)
        float agg0 = 0.f, agg1 = 0.f, agg2 = 0.f, agg3 = 0.f;
        const int h0 = 4 * lane;

        if (cnt > 0) {
            ull wA[11], wB[11];
            {
                const float4* __restrict__ w11v =
                    (const float4*)(W1 + 11 * HH);
                const float4 wf11 = __ldg(&w11v[lane]);
                #pragma unroll
                for (int f = 0; f < 11; f++) {
                    float4 wf = __ldg(&((const float4*)(W1 + f * HH))[lane]);
                    if (f == 2) {   // fold duplicated feature: msg[11] == msg[2]
                        wf.x += wf11.x; wf.y += wf11.y;
                        wf.z += wf11.z; wf.w += wf11.w;
                    }
                    wA[f] = pack2(wf.x, wf.y);
                    wB[f] = pack2(wf.z, wf.w);
                }
            }
            const float4 bv = __ldg(&((const float4*)b1)[lane]);
            const ull bA = pack2(bv.x, bv.y);
            const ull bB = pack2(bv.z, bv.w);
            const ull HALF2 = pack2(0.5f, 0.5f);
            const ull ABSM  = 0x7fffffff7fffffffULL;
            ull aggA = pack2(0.f, 0.f), aggB = pack2(0.f, 0.f);

            unsigned raddr = smem_u32(&s_feat[p][0]);
            for (int e = 0; e < cnt; e++, raddr += FROW * 4) {
                ull q0, q1, q2, q3;
                ull tA = bA, tB = bB;
                lds2x64(q0, q1, raddr);          // f0, f1
                lds2x64(q2, q3, raddr + 16);     // f2, f3
                tA = fma2(q0, wA[0], tA);  tB = fma2(q0, wB[0], tB);
                tA = fma2(q1, wA[1], tA);  tB = fma2(q1, wB[1], tB);
                lds2x64(q0, q1, raddr + 32);     // f4, f5
                tA = fma2(q2, wA[2], tA);  tB = fma2(q2, wB[2], tB);
                tA = fma2(q3, wA[3], tA);  tB = fma2(q3, wB[3], tB);
                lds2x64(q2, q3, raddr + 48);     // f6, f7
                tA = fma2(q0, wA[4], tA);  tB = fma2(q0, wB[4], tB);
                tA = fma2(q1, wA[5], tA);  tB = fma2(q1, wB[5], tB);
                lds2x64(q0, q1, raddr + 64);     // f8, f9
                tA = fma2(q2, wA[6], tA);  tB = fma2(q2, wB[6], tB);
                tA = fma2(q3, wA[7], tA);  tB = fma2(q3, wB[7], tB);
                lds64(q2, raddr + 80);           // f10
                tA = fma2(q0, wA[8], tA);  tB = fma2(q0, wB[8], tB);
                tA = fma2(q1, wA[9], tA);  tB = fma2(q1, wB[9], tB);
                tA = fma2(q2, wA[10], tA); tB = fma2(q2, wB[10], tB);

                // exact packed relu-accumulate: relu(x) = (x + |x|) * 0.5
                const ull sA = add2(tA, tA & ABSM);
                const ull sB = add2(tB, tB & ABSM);
                aggA = fma2(sA, HALF2, aggA);
                aggB = fma2(sB, HALF2, aggB);
            }
            unpack2(aggA, agg0, agg1);
            unpack2(aggB, agg2, agg3);
        }

        // agg @ W2[:, 0:2]  (outputs 2..6 are dead code in the reference)
        float pa0, pa1;
        pa0 = agg0 * __ldg(&W2[(h0 + 0) * 7 + 0]);
        pa0 = fmaf(agg1, __ldg(&W2[(h0 + 1) * 7 + 0]), pa0);
        pa0 = fmaf(agg2, __ldg(&W2[(h0 + 2) * 7 + 0]), pa0);
        pa0 = fmaf(agg3, __ldg(&W2[(h0 + 3) * 7 + 0]), pa0);
        pa1 = agg0 * __ldg(&W2[(h0 + 0) * 7 + 1]);
        pa1 = fmaf(agg1, __ldg(&W2[(h0 + 1) * 7 + 1]), pa1);
        pa1 = fmaf(agg2, __ldg(&W2[(h0 + 2) * 7 + 1]), pa1);
        pa1 = fmaf(agg3, __ldg(&W2[(h0 + 3) * 7 + 1]), pa1);
        #pragma unroll
        for (int sh = 16; sh > 0; sh >>= 1) {
            pa0 += __shfl_xor_sync(FULL, pa0, sh);
            pa1 += __shfl_xor_sync(FULL, pa1, sh);
        }
        o0 = pa0 + __ldg(&b2[0]);   // all lanes hold the reduced value
        o1 = pa1 + __ldg(&b2[1]);
    }

    // ============ Phase 4: epilogue (all lanes redundantly) ==================
    {
        const float vx = __shfl_sync(FULL, xv, 2);
        const float vy = __shfl_sync(FULL, xv, 3);
        float nvx = vx, nvy = vy, npx = pix, npy = piy;

        if (is_cell) {
            float ax = tanhf(o0) * ACC_SCALEF;
            float ay = tanhf(o1) * ACC_SCALEF;
            float ux = vx + ax, uy = vy + ay;
            float sp = sqrtf(ux * ux + uy * uy);
            float sc = fminf(1.0f, MAX_VELF / (sp + 1e-12f));
            ux *= sc; uy *= sc;
            npx = pix + ux; npx -= floorf(npx);
            npy = piy + uy; npy -= floorf(npy);
            const float u0 = __shfl_sync(FULL, nz, 0);
            const float u1 = __shfl_sync(FULL, nz, 1);
            const float u2 = __shfl_sync(FULL, nz, 2);
            const float nm = (u2 > 0.5f) ? 1.0f : 0.0f;
            nvx = ux + (u0 * 2.0f - 1.0f) * NOISEF * nm;
            nvy = uy + (u1 * 2.0f - 1.0f) * NOISEF * nm;
        }

        const bool dead     =  is_cell && (deg_cell < 1);
        const bool consumed = !is_cell && (deg_cell >= 1);
        const float keep = (dead || consumed) ? 0.0f : 1.0f;

        if (lane < CC) {
            float val = xv;                       // lanes 4..9: passthrough fields
            if (lane == 0) val = npx;
            else if (lane == 1) val = npy;
            else if (lane == 2) val = nvx;
            else if (lane == 3) val = nvy;
            out[(size_t)grow * CC + lane] = val * keep;
        }
    }
}

// ---------------------------------------------------------------------------
extern "C" void kernel_launch(void* const* d_in, const int* in_sizes, int n_in,
                              void* d_out, int out_size)
{
    const float* x       = (const float*)d_in[0];
    const float* W1      = (const float*)d_in[1];
    const float* b1      = (const float*)d_in[2];
    const float* W2      = (const float*)d_in[3];
    const float* b2      = (const float*)d_in[4];
    const float* noise_u = (const float*)d_in[5];
    float* out = (float*)d_out;

    build_grid_kernel<<<BB, TPB_G>>>(x);
    fused_kernel<<<(BB * MM) / NPW, 256>>>(x, W1, b1, W2, b2, noise_u, out);
}

// round 11
// speedup vs baseline: 1.2504x; 1.0156x over previous
#include <cuda_runtime.h>
#include <math.h>

#define BB 8
#define MM 3072
#define CC 10
#define HH 128
#define KK 32
#define GG 24                 // grid cells per axis; 1/24 > 0.04 radius
#define NCELL (GG * GG)       // 576
#define CAP 48                // per-particle candidate-hit capacity (lambda~15)
#define NPW 8                 // warps per block
#define FROW 28               // feature row stride in floats (112B, conflict-free STS.128)
#define NBLK 296              // 2 blocks per SM on 148 SMs, single wave
#define NWARPS (NBLK * NPW)   // 2368 persistent warps
#define TOTP (BB * MM)        // 24576 particles
#define PPW ((TOTP + NWARPS - 1) / NWARPS)   // 11 particles per warp (ragged)
#define RADIUSF 0.04f
#define ACC_SCALEF 0.02f
#define MAX_VELF 0.02f
#define NOISEF 0.002f

typedef unsigned long long ull;

// Scratch (no cudaMalloc allowed)
__device__ float4 g_sorted[BB * MM];            // {x, y, id_as_float_bits, pad}
__device__ int    g_cell_off[BB * (NCELL + 1)]; // exclusive offsets per batch

__device__ __forceinline__ int cell_of(float p) {
    int c = (int)(p * (float)GG);
    return c > GG - 1 ? GG - 1 : c;
}

// ---- f32x2 packed helpers (sm_100+) ---------------------------------------
__device__ __forceinline__ ull pack2(float lo, float hi) {
    ull d; asm("mov.b64 %0, {%1, %2};" : "=l"(d) : "f"(lo), "f"(hi)); return d;
}
__device__ __forceinline__ void unpack2(ull v, float &lo, float &hi) {
    asm("mov.b64 {%0, %1}, %2;" : "=f"(lo), "=f"(hi) : "l"(v));
}
__device__ __forceinline__ ull fma2(ull a, ull b, ull c) {
    ull d; asm("fma.rn.f32x2 %0, %1, %2, %3;" : "=l"(d) : "l"(a), "l"(b), "l"(c));
    return d;
}
__device__ __forceinline__ ull add2(ull a, ull b) {
    ull d; asm("add.rn.f32x2 %0, %1, %2;" : "=l"(d) : "l"(a), "l"(b));
    return d;
}
__device__ __forceinline__ void lds2x64(ull &a, ull &b, unsigned addr) {
    asm volatile("ld.shared.v2.b64 {%0, %1}, [%2];" : "=l"(a), "=l"(b) : "r"(addr));
}
__device__ __forceinline__ void lds64(ull &a, unsigned addr) {
    asm volatile("ld.shared.b64 %0, [%1];" : "=l"(a) : "r"(addr));
}
__device__ __forceinline__ unsigned smem_u32(const void* p) {
    return (unsigned)__cvta_generic_to_shared(p);
}

// ---------------------------------------------------------------------------
// Kernel 0: build cell-sorted particle list. One block per batch.
// ---------------------------------------------------------------------------
#define TPB_G 1024
__global__ void __launch_bounds__(TPB_G) build_grid_kernel(const float* __restrict__ x)
{
    __shared__ int s_cnt[NCELL];
    __shared__ int s_wsum[TPB_G / 32];
    __shared__ int s_cur[NCELL];

    const int b = blockIdx.x;
    const int tid = threadIdx.x;
    const int wid = tid >> 5, lane = tid & 31;
    const unsigned FULL = 0xffffffffu;
    const float* xb = x + (size_t)b * MM * CC;

    if (tid < NCELL) s_cnt[tid] = 0;
    __syncthreads();

    int   myc[MM / TPB_G];
    float mpx[MM / TPB_G], mpy[MM / TPB_G];
    #pragma unroll
    for (int r = 0; r < MM / TPB_G; r++) {
        const int i = tid + r * TPB_G;
        const float px = xb[(size_t)i * CC + 0];
        const float py = xb[(size_t)i * CC + 1];
        const int c = cell_of(py) * GG + cell_of(px);
        myc[r] = c; mpx[r] = px; mpy[r] = py;
        atomicAdd(&s_cnt[c], 1);
    }
    __syncthreads();

    // hierarchical exclusive scan over NCELL=576
    int val = (tid < NCELL) ? s_cnt[tid] : 0;
    int incl = val;
    #pragma unroll
    for (int o = 1; o < 32; o <<= 1) {
        int v = __shfl_up_sync(FULL, incl, o);
        if (lane >= o) incl += v;
    }
    if (lane == 31) s_wsum[wid] = incl;
    __syncthreads();
    if (wid == 0) {
        int wv = (lane < TPB_G / 32) ? s_wsum[lane] : 0;
        int wi = wv;
        #pragma unroll
        for (int o = 1; o < 32; o <<= 1) {
            int v = __shfl_up_sync(FULL, wi, o);
            if (lane >= o) wi += v;
        }
        if (lane < TPB_G / 32) s_wsum[lane] = wi - wv;
    }
    __syncthreads();
    if (tid < NCELL) {
        const int excl = s_wsum[wid] + incl - val;
        s_cur[tid] = excl;
        g_cell_off[b * (NCELL + 1) + tid] = excl;
    }
    if (tid == 0) g_cell_off[b * (NCELL + 1) + NCELL] = MM;
    __syncthreads();

    #pragma unroll
    for (int r = 0; r < MM / TPB_G; r++) {
        const int i = tid + r * TPB_G;
        const int slot = atomicAdd(&s_cur[myc[r]], 1);
        g_sorted[(size_t)b * MM + slot] =
            make_float4(mpx[r], mpy[r], __int_as_float(i), 0.0f);
    }
}

// ---------------------------------------------------------------------------
// Persistent fused kernel: each warp processes ~11 particles, packed weights
// held in registers across particles; next particle's sorted entry prefetched
// one iteration ahead.
// ---------------------------------------------------------------------------
__global__ void __launch_bounds__(256, 2) fused_kernel(
    const float* __restrict__ x,  const float* __restrict__ W1,
    const float* __restrict__ b1, const float* __restrict__ W2,
    const float* __restrict__ b2, const float* __restrict__ noise_u,
    float* __restrict__ out)
{
    __shared__ float s_cdx[NPW][CAP], s_cdy[NPW][CAP], s_cds[NPW][CAP];
    __shared__ int   s_cj [NPW][CAP];
    __shared__ __align__(16) float s_feat[NPW][KK * FROW];
    __shared__ int   s_astart[NPW][9];
    __shared__ int   s_bound [NPW][10];

    const unsigned FULL = 0xffffffffu;
    const int warp = threadIdx.x >> 5;
    const int lane = threadIdx.x & 31;
    const int p = warp;
    const int wg = blockIdx.x * NPW + warp;      // persistent warp id

    // ---- weight prologue: ONCE per warp (amortized over ~11 particles) ------
    ull wA[11], wB[11];
    {
        const float4 wf11 = __ldg(&((const float4*)(W1 + 11 * HH))[lane]);
        #pragma unroll
        for (int f = 0; f < 11; f++) {
            float4 wf = __ldg(&((const float4*)(W1 + f * HH))[lane]);
            if (f == 2) {   // fold duplicated feature: msg[11] == msg[2]
                wf.x += wf11.x; wf.y += wf11.y;
                wf.z += wf11.z; wf.w += wf11.w;
            }
            wA[f] = pack2(wf.x, wf.y);
            wB[f] = pack2(wf.z, wf.w);
        }
    }
    const float4 bv = __ldg(&((const float4*)b1)[lane]);
    const ull bA = pack2(bv.x, bv.y);
    const ull bB = pack2(bv.z, bv.w);
    const int h0 = 4 * lane;
    float w2c0[4], w2c1[4];
    #pragma unroll
    for (int i = 0; i < 4; i++) {
        w2c0[i] = __ldg(&W2[(h0 + i) * 7 + 0]);
        w2c1[i] = __ldg(&W2[(h0 + i) * 7 + 1]);
    }
    const float b2v0 = __ldg(&b2[0]);
    const float b2v1 = __ldg(&b2[1]);
    const ull HALF2 = pack2(0.5f, 0.5f);
    const ull ABSM  = 0x7fffffff7fffffffULL;

    // prefetch first particle's sorted entry
    float4 me_pref = (wg < TOTP) ? g_sorted[wg] : make_float4(0.f, 0.f, 0.f, 0.f);

    for (int k = 0; k < PPW; k++) {
        const int sidx = wg + k * NWARPS;        // interleaved assignment
        if (sidx >= TOTP) break;                 // warp-uniform
        const float4 me = me_pref;
        {
            const int snext = sidx + NWARPS;
            if (snext < TOTP) me_pref = g_sorted[snext];
        }
        const int b = sidx / MM;
        const int myslot = sidx - b * MM;
        const float pix = me.x, piy = me.y;
        const int   myid = __float_as_int(me.z);
        const int   grow = b * MM + myid;

        // ---- early prefetch: own row + noise (used ~2000 cycles later) ------
        const float xv = (lane < CC) ? __ldg(&x[(size_t)grow * CC + lane]) : 0.0f;
        const float nz = (lane < 3)  ? __ldg(&noise_u[(size_t)grow * 3 + lane]) : 0.0f;
        const bool is_cell = (__shfl_sync(FULL, xv, 4) == 1.0f);

        // ======================= Phase 1: search =============================
        const int cix = cell_of(pix);
        const int ciy = cell_of(piy);
        int len = 0, t0 = 0;
        if (lane < 9) {
            int cy = ciy + (lane / 3) - 1; if (cy < 0) cy += GG; if (cy >= GG) cy -= GG;
            int cx = cix + (lane % 3) - 1; if (cx < 0) cx += GG; if (cx >= GG) cx -= GG;
            const int c = cy * GG + cx;
            t0  = g_cell_off[b * (NCELL + 1) + c];
            len = g_cell_off[b * (NCELL + 1) + c + 1] - t0;
        }
        int incl = len;
        #pragma unroll
        for (int o = 1; o < 16; o <<= 1) {
            int v = __shfl_up_sync(FULL, incl, o);
            if (lane >= o) incl += v;
        }
        const int T = __shfl_sync(FULL, incl, 8);
        if (lane < 9) {
            const int excl = incl - len;
            s_astart[p][lane] = t0 - excl;
            s_bound [p][lane] = excl;
        }
        __syncwarp();

        const float4* __restrict__ sb = g_sorted + (size_t)b * MM;

        auto slot_of = [&](int kk) -> int {
            int q = 0;
            #pragma unroll
            for (int t = 1; t < 9; t++)
                if (kk >= s_bound[p][t]) q = t;
            return s_astart[p][q] + kk;
        };

        // prefetch BOTH rounds' candidates (one global round-trip)
        const int k0 = lane, k1 = lane + 32;
        int ts0 = 0, ts1 = 0;
        float4 cand0 = make_float4(0.f, 0.f, 0.f, 0.f);
        float4 cand1 = make_float4(0.f, 0.f, 0.f, 0.f);
        if (k0 < T) { ts0 = slot_of(k0); cand0 = __ldg(&sb[ts0]); }
        if (k1 < T) { ts1 = slot_of(k1); cand1 = __ldg(&sb[ts1]); }

        int hits = 0;
        #pragma unroll
        for (int rnd = 0; rnd < 2; rnd++) {
            const int     kc   = rnd ? k1 : k0;
            const int     tslt = rnd ? ts1 : ts0;
            const float4  cand = rnd ? cand1 : cand0;
            bool pred = false;
            float dx = 0.f, dy = 0.f, dist = 0.f;
            if (kc < T) {
                dx = pix - cand.x; dx -= rintf(dx);
                dy = piy - cand.y; dy -= rintf(dy);
                dist = sqrtf(dx * dx + dy * dy + 1e-12f);
                pred = (dist < RADIUSF) && (tslt != myslot);
            }
            const unsigned m = __ballot_sync(FULL, pred);
            if (pred) {
                const int pos = hits + __popc(m & ((1u << lane) - 1));
                if (pos < CAP) {
                    s_cj [p][pos] = __float_as_int(cand.z);
                    s_cdx[p][pos] = dx;
                    s_cdy[p][pos] = dy;
                    s_cds[p][pos] = dist;
                }
            }
            hits += __popc(m);
        }
        // rare: T > 64
        for (int base = 64; base < T; base += 32) {
            const int kc = base + lane;
            bool pred = false;
            int  cid = 0;
            float dx = 0.f, dy = 0.f, dist = 0.f;
            if (kc < T) {
                const int tslot = slot_of(kc);
                const float4 cand = __ldg(&sb[tslot]);
                dx = pix - cand.x; dx -= rintf(dx);
                dy = piy - cand.y; dy -= rintf(dy);
                dist = sqrtf(dx * dx + dy * dy + 1e-12f);
                pred = (dist < RADIUSF) && (tslot != myslot);
                cid = __float_as_int(cand.z);
            }
            const unsigned m = __ballot_sync(FULL, pred);
            if (pred) {
                const int pos = hits + __popc(m & ((1u << lane) - 1));
                if (pos < CAP) {
                    s_cj [p][pos] = cid;
                    s_cdx[p][pos] = dx;
                    s_cdy[p][pos] = dy;
                    s_cds[p][pos] = dist;
                }
            }
            hits += __popc(m);
        }
        if (hits > CAP) hits = CAP;
        __syncwarp();

        // rare: rank-select KK nearest (edge order is dead: edges are summed)
        if (hits > KK) {
            float* stage = &s_feat[p][0];
            int*   stagei = (int*)&s_feat[p][3 * KK];
            for (int h = lane; h < hits; h += 32) {
                const float dh = s_cds[p][h];
                int rank = 0;
                for (int g2 = 0; g2 < hits; g2++) {
                    const float dg = s_cds[p][g2];
                    rank += (dg < dh) || (dg == dh && g2 < h);
                }
                if (rank < KK) {
                    stage[rank]          = s_cdx[p][h];
                    stage[KK + rank]     = s_cdy[p][h];
                    stage[2 * KK + rank] = dh;
                    stagei[rank]         = s_cj[p][h];
                }
            }
            __syncwarp();
            if (lane < KK) {
                s_cdx[p][lane] = stage[lane];
                s_cdy[p][lane] = stage[KK + lane];
                s_cds[p][lane] = stage[2 * KK + lane];
                s_cj [p][lane] = stagei[lane];
            }
            hits = KK;
            __syncwarp();
        }
        const int cnt = hits;

        // ============== Phase 2: gather features (lane = edge) ===============
        float c4v = 0.0f;
        if (lane < cnt) {
            const int j = s_cj[p][lane];
            const float2* xp = (const float2*)(x + ((size_t)b * MM + j) * CC);
            const float2 a2 = __ldg(&xp[2]);    // cell, rest0
            c4v = a2.x;
            if (is_cell) {
                const float2 a1 = __ldg(&xp[1]);
                const float2 a3 = __ldg(&xp[3]);
                const float2 a4 = __ldg(&xp[4]);
                float4* row = (float4*)&s_feat[p][lane * FROW];
                const float ds = s_cds[p][lane];
                const float dx = s_cdx[p][lane];
                const float dy = s_cdy[p][lane];
                row[0] = make_float4(a1.x, a1.x, a1.y, a1.y);
                row[1] = make_float4(a2.x, a2.x, a2.y, a2.y);
                row[2] = make_float4(a3.x, a3.x, a3.y, a3.y);
                row[3] = make_float4(a4.x, a4.x, a4.y, a4.y);
                row[4] = make_float4(ds,   ds,   dx,   dx);
                row[5] = make_float4(dy,   dy,   0.f,  0.f);
            }
        }
        const int deg_cell = __popc(__ballot_sync(FULL, (lane < cnt) && (c4v == 1.0f)));
        __syncwarp();

        // ===================== Phase 3: edge MLP (packed) ====================
        float o0 = 0.0f, o1 = 0.0f;

        if (is_cell) {
            float agg0 = 0.f, agg1 = 0.f, agg2 = 0.f, agg3 = 0.f;
            if (cnt > 0) {
                ull aggA = pack2(0.f, 0.f), aggB = pack2(0.f, 0.f);
                unsigned raddr = smem_u32(&s_feat[p][0]);
                for (int e = 0; e < cnt; e++, raddr += FROW * 4) {
                    ull q0, q1, q2, q3;
                    ull tA = bA, tB = bB;
                    lds2x64(q0, q1, raddr);          // f0, f1
                    lds2x64(q2, q3, raddr + 16);     // f2, f3
                    tA = fma2(q0, wA[0], tA);  tB = fma2(q0, wB[0], tB);
                    tA = fma2(q1, wA[1], tA);  tB = fma2(q1, wB[1], tB);
                    lds2x64(q0, q1, raddr + 32);     // f4, f5
                    tA = fma2(q2, wA[2], tA);  tB = fma2(q2, wB[2], tB);
                    tA = fma2(q3, wA[3], tA);  tB = fma2(q3, wB[3], tB);
                    lds2x64(q2, q3, raddr + 48);     // f6, f7
                    tA = fma2(q0, wA[4], tA);  tB = fma2(q0, wB[4], tB);
                    tA = fma2(q1, wA[5], tA);  tB = fma2(q1, wB[5], tB);
                    lds2x64(q0, q1, raddr + 64);     // f8, f9
                    tA = fma2(q2, wA[6], tA);  tB = fma2(q2, wB[6], tB);
                    tA = fma2(q3, wA[7], tA);  tB = fma2(q3, wB[7], tB);
                    lds64(q2, raddr + 80);           // f10
                    tA = fma2(q0, wA[8], tA);  tB = fma2(q0, wB[8], tB);
                    tA = fma2(q1, wA[9], tA);  tB = fma2(q1, wB[9], tB);
                    tA = fma2(q2, wA[10], tA); tB = fma2(q2, wB[10], tB);

                    // exact packed relu-accumulate: relu(x) = (x + |x|) * 0.5
                    const ull sA = add2(tA, tA & ABSM);
                    const ull sB = add2(tB, tB & ABSM);
                    aggA = fma2(sA, HALF2, aggA);
                    aggB = fma2(sB, HALF2, aggB);
                }
                unpack2(aggA, agg0, agg1);
                unpack2(aggB, agg2, agg3);
            }

            float pa0, pa1;
            pa0 = agg0 * w2c0[0];
            pa0 = fmaf(agg1, w2c0[1], pa0);
            pa0 = fmaf(agg2, w2c0[2], pa0);
            pa0 = fmaf(agg3, w2c0[3], pa0);
            pa1 = agg0 * w2c1[0];
            pa1 = fmaf(agg1, w2c1[1], pa1);
            pa1 = fmaf(agg2, w2c1[2], pa1);
            pa1 = fmaf(agg3, w2c1[3], pa1);
            #pragma unroll
            for (int sh = 16; sh > 0; sh >>= 1) {
                pa0 += __shfl_xor_sync(FULL, pa0, sh);
                pa1 += __shfl_xor_sync(FULL, pa1, sh);
            }
            o0 = pa0 + b2v0;   // all lanes hold the reduced value
            o1 = pa1 + b2v1;
        }

        // ============ Phase 4: epilogue (all lanes redundantly) ==============
        {
            const float vx = __shfl_sync(FULL, xv, 2);
            const float vy = __shfl_sync(FULL, xv, 3);
            float nvx = vx, nvy = vy, npx = pix, npy = piy;

            if (is_cell) {
                float ax = tanhf(o0) * ACC_SCALEF;
                float ay = tanhf(o1) * ACC_SCALEF;
                float ux = vx + ax, uy = vy + ay;
                float sp = sqrtf(ux * ux + uy * uy);
                float sc = fminf(1.0f, MAX_VELF / (sp + 1e-12f));
                ux *= sc; uy *= sc;
                npx = pix + ux; npx -= floorf(npx);
                npy = piy + uy; npy -= floorf(npy);
                const float u0 = __shfl_sync(FULL, nz, 0);
                const float u1 = __shfl_sync(FULL, nz, 1);
                const float u2 = __shfl_sync(FULL, nz, 2);
                const float nm = (u2 > 0.5f) ? 1.0f : 0.0f;
                nvx = ux + (u0 * 2.0f - 1.0f) * NOISEF * nm;
                nvy = uy + (u1 * 2.0f - 1.0f) * NOISEF * nm;
            }

            const bool dead     =  is_cell && (deg_cell < 1);
            const bool consumed = !is_cell && (deg_cell >= 1);
            const float keep = (dead || consumed) ? 0.0f : 1.0f;

            if (lane < CC) {
                float val = xv;                   // lanes 4..9: passthrough fields
                if (lane == 0) val = npx;
                else if (lane == 1) val = npy;
                else if (lane == 2) val = nvx;
                else if (lane == 3) val = nvy;
                out[(size_t)grow * CC + lane] = val * keep;
            }
        }
    }
}

// ---------------------------------------------------------------------------
extern "C" void kernel_launch(void* const* d_in, const int* in_sizes, int n_in,
                              void* d_out, int out_size)
{
    const float* x       = (const float*)d_in[0];
    const float* W1      = (const float*)d_in[1];
    const float* b1      = (const float*)d_in[2];
    const float* W2      = (const float*)d_in[3];
    const float* b2      = (const float*)d_in[4];
    const float* noise_u = (const float*)d_in[5];
    float* out = (float*)d_out;

    build_grid_kernel<<<BB, TPB_G>>>(x);
    fused_kernel<<<NBLK, NPW * 32>>>(x, W1, b1, W2, b2, noise_u, out);
}